// round 2
// baseline (speedup 1.0000x reference)
#include <cuda_runtime.h>
#include <cuda_bf16.h>

// ----------------------------------------------------------------------------
// GNNLayer: out = relu(x @ W^T + b); out[col[e],0] += x[e,0]
// x: [N,512] f32, edge_index: [2,N] (int32 on device), W: [512,512] f32, b: [512] f32
// ----------------------------------------------------------------------------

#define IN_DIM  512
#define OUT_DIM 512

// Scratch: transposed W (Wt[i][o] = W[o][i]) so GEMM B-tile loads are coalesced.
__device__ float g_Wt[IN_DIM * OUT_DIM];

// ---------------- W transpose (512x512, runs once per replay, ~few us) -------
__global__ void transpose_W_kernel(const float* __restrict__ W) {
    __shared__ float tile[32][33];
    int x = blockIdx.x * 32 + threadIdx.x;   // input col (i)
    int y = blockIdx.y * 32 + threadIdx.y;   // input row (o)
    #pragma unroll
    for (int j = 0; j < 32; j += 8)
        tile[threadIdx.y + j][threadIdx.x] = W[(y + j) * IN_DIM + x];
    __syncthreads();
    x = blockIdx.y * 32 + threadIdx.x;       // output col (o)
    y = blockIdx.x * 32 + threadIdx.y;       // output row (i)
    #pragma unroll
    for (int j = 0; j < 32; j += 8)
        g_Wt[(y + j) * OUT_DIM + x] = tile[threadIdx.x][threadIdx.y + j];
}

// ---------------- SGEMM + bias + relu ----------------------------------------
// C[M, 512] = relu(A[M,512] @ Wt[512,512] + b)
// Block tile 128x128, BK=8, 256 threads, 8x8 register tile per thread.
#define BM 128
#define BN 128
#define BK 8
#define TM 8
#define TN 8

__global__ __launch_bounds__(256, 2)
void gemm_bias_relu_kernel(const float* __restrict__ A,
                           const float* __restrict__ bias,
                           float* __restrict__ C,
                           int M) {
    __shared__ float As[BK][BM];   // stored transposed: As[k][m]
    __shared__ float Bs[BK][BN];

    const int tid = threadIdx.x;
    const int blockCol = blockIdx.x;       // 0..3 over N=512
    const int blockRow = blockIdx.y;       // over M

    const int row0 = blockRow * BM;
    const int col0 = blockCol * BN;

    // A loader: 128 rows x 8 cols, 2 threads per row, float4 each
    const int aRow = tid >> 1;             // 0..127
    const int aCol = (tid & 1) * 4;        // 0 or 4
    // B loader: 8 rows x 128 cols, 32 threads per row, float4 each
    const int bRow = tid >> 5;             // 0..7
    const int bCol = (tid & 31) * 4;       // 0..124

    // compute mapping: 16x16 thread grid, each 8x8 outputs
    const int ty = tid >> 4;               // 0..15
    const int tx = tid & 15;               // 0..15

    const int gARow = row0 + aRow;
    const bool aValid = (gARow < M);
    const float* Aptr = A + (size_t)gARow * IN_DIM + aCol;
    const float* Bptr = g_Wt + (size_t)bRow * OUT_DIM + col0 + bCol;

    float acc[TM][TN];
    #pragma unroll
    for (int i = 0; i < TM; i++)
        #pragma unroll
        for (int j = 0; j < TN; j++)
            acc[i][j] = 0.0f;

    float ra[TM], rb[TN];

    for (int kt = 0; kt < IN_DIM; kt += BK) {
        // load A tile (guarded rows), store transposed
        float4 a4 = aValid ? *reinterpret_cast<const float4*>(Aptr + kt)
                           : make_float4(0.f, 0.f, 0.f, 0.f);
        As[aCol + 0][aRow] = a4.x;
        As[aCol + 1][aRow] = a4.y;
        As[aCol + 2][aRow] = a4.z;
        As[aCol + 3][aRow] = a4.w;

        // load B tile (Wt rows kt+bRow)
        float4 b4 = *reinterpret_cast<const float4*>(Bptr + (size_t)kt * OUT_DIM);
        *reinterpret_cast<float4*>(&Bs[bRow][bCol]) = b4;

        __syncthreads();

        #pragma unroll
        for (int k = 0; k < BK; k++) {
            #pragma unroll
            for (int i = 0; i < TM; i++) ra[i] = As[k][ty * TM + i];
            #pragma unroll
            for (int j = 0; j < TN; j++) rb[j] = Bs[k][tx * TN + j];
            #pragma unroll
            for (int i = 0; i < TM; i++)
                #pragma unroll
                for (int j = 0; j < TN; j++)
                    acc[i][j] = fmaf(ra[i], rb[j], acc[i][j]);
        }
        __syncthreads();
    }

    // epilogue: bias + relu + store (float4 x2 per row)
    float bv[TN];
    #pragma unroll
    for (int j = 0; j < TN; j++) bv[j] = bias[col0 + tx * TN + j];

    #pragma unroll
    for (int i = 0; i < TM; i++) {
        int row = row0 + ty * TM + i;
        if (row < M) {
            float* cp = C + (size_t)row * OUT_DIM + col0 + tx * TN;
            float4 o0, o1;
            o0.x = fmaxf(acc[i][0] + bv[0], 0.f);
            o0.y = fmaxf(acc[i][1] + bv[1], 0.f);
            o0.z = fmaxf(acc[i][2] + bv[2], 0.f);
            o0.w = fmaxf(acc[i][3] + bv[3], 0.f);
            o1.x = fmaxf(acc[i][4] + bv[4], 0.f);
            o1.y = fmaxf(acc[i][5] + bv[5], 0.f);
            o1.z = fmaxf(acc[i][6] + bv[6], 0.f);
            o1.w = fmaxf(acc[i][7] + bv[7], 0.f);
            *reinterpret_cast<float4*>(cp)     = o0;
            *reinterpret_cast<float4*>(cp + 4) = o1;
        }
    }
}

// ---------------- scatter-add on column 0 -------------------------------------
// out[col[e], 0] += x[e, 0], col = edge_index[1] (second row of [2,N], int32 on device)
__global__ void scatter_add_col0_kernel(const float* __restrict__ x,
                                        const int* __restrict__ edge_index,
                                        float* __restrict__ out,
                                        int E) {
    int e = blockIdx.x * blockDim.x + threadIdx.x;
    if (e < E) {
        int c = edge_index[E + e];          // row 1 of [2,E] int32
        atomicAdd(&out[(size_t)c * OUT_DIM], x[(size_t)e * IN_DIM]);
    }
}

// ---------------- launch ------------------------------------------------------
extern "C" void kernel_launch(void* const* d_in, const int* in_sizes, int n_in,
                              void* d_out, int out_size) {
    const float* x   = (const float*)d_in[0];
    const int*   ei  = (const int*)d_in[1];      // int64 in reference -> int32 on device
    const float* W   = (const float*)d_in[2];
    const float* b   = (const float*)d_in[3];
    float*       out = (float*)d_out;

    const int M = in_sizes[0] / IN_DIM;   // number of rows of x (= N)
    const int E = in_sizes[1] / 2;        // edges

    // 1) transpose W into scratch
    transpose_W_kernel<<<dim3(16, 16), dim3(32, 8)>>>(W);

    // 2) GEMM + bias + relu
    dim3 grid(OUT_DIM / BN, (M + BM - 1) / BM);
    gemm_bias_relu_kernel<<<grid, 256>>>(x, b, out, M);

    // 3) scatter-add into column 0
    scatter_add_col0_kernel<<<(E + 255) / 256, 256>>>(x, ei, out, E);
}

// round 5
// speedup vs baseline: 2.1306x; 2.1306x over previous
#include <cuda_runtime.h>
#include <cuda_bf16.h>
#include <cstdint>

// ----------------------------------------------------------------------------
// GNNLayer: out = relu(x @ W^T + b); out[col[e],0] += x[e,0]
// Ampere-style mma.sync bf16 hi/lo split GEMM (non-"a" PTX features only).
// ----------------------------------------------------------------------------

#define IN_DIM  512
#define OUT_DIM 512
#define BM      128
#define BN      128
#define BK      32
#define NCHUNK  (IN_DIM / BK)   // 16
#define THREADS 256

// smem: rows padded to 80 bytes (32 bf16 = 64B + 16B pad) -> ldmatrix conflict-free
#define ROWB    80
#define A_HI    0
#define A_LO    (BM * ROWB)          // 10240
#define B_HI    (2 * BM * ROWB)      // 20480
#define B_LO    (3 * BM * ROWB)      // 30720
#define STAGE   (4 * BM * ROWB)      // 40960
#define SM_TOTAL (2 * STAGE)         // 81920

// W split into bf16 hi/lo; W is [OUT,IN] = [N,K], K contiguous (mma col-major B)
__device__ __nv_bfloat16 g_Whi[OUT_DIM * IN_DIM];
__device__ __nv_bfloat16 g_Wlo[OUT_DIM * IN_DIM];

__device__ __forceinline__ uint32_t smem_u32(const void* p) {
    uint32_t a;
    asm("{ .reg .u64 t; cvta.to.shared.u64 t, %1; cvt.u32.u64 %0, t; }" : "=r"(a) : "l"(p));
    return a;
}

__device__ __forceinline__ void ldx4(uint32_t r[4], uint32_t addr) {
    asm volatile("ldmatrix.sync.aligned.m8n8.x4.shared.b16 {%0,%1,%2,%3}, [%4];"
                 : "=r"(r[0]), "=r"(r[1]), "=r"(r[2]), "=r"(r[3]) : "r"(addr));
}
__device__ __forceinline__ void ldx2(uint32_t r[2], uint32_t addr) {
    asm volatile("ldmatrix.sync.aligned.m8n8.x2.shared.b16 {%0,%1}, [%2];"
                 : "=r"(r[0]), "=r"(r[1]) : "r"(addr));
}
__device__ __forceinline__ void mma16816(float c[4], const uint32_t a[4], const uint32_t b[2]) {
    asm volatile("mma.sync.aligned.m16n8k16.row.col.f32.bf16.bf16.f32 "
                 "{%0,%1,%2,%3}, {%4,%5,%6,%7}, {%8,%9}, {%0,%1,%2,%3};"
                 : "+f"(c[0]), "+f"(c[1]), "+f"(c[2]), "+f"(c[3])
                 : "r"(a[0]), "r"(a[1]), "r"(a[2]), "r"(a[3]), "r"(b[0]), "r"(b[1]));
}
__device__ __forceinline__ void cp16(uint32_t dst, const void* src) {
    asm volatile("cp.async.cg.shared.global [%0], [%1], 16;"
                 :: "r"(dst), "l"(__cvta_generic_to_global(src)));
}

// ---------------- W split prep kernel ----------------------------------------
__global__ void split_W_kernel(const float* __restrict__ W) {
    int i = blockIdx.x * blockDim.x + threadIdx.x;
    if (i < OUT_DIM * IN_DIM) {
        float v = W[i];
        __nv_bfloat16 hi = __float2bfloat16_rn(v);
        g_Whi[i] = hi;
        g_Wlo[i] = __float2bfloat16_rn(v - __bfloat162float(hi));
    }
}

// ---------------- main GEMM kernel (mma.sync) ---------------------------------
__global__ __launch_bounds__(THREADS)
void gemm_mma_kernel(const float* __restrict__ A,
                     const float* __restrict__ bias,
                     float* __restrict__ C, int M) {
    extern __shared__ char smem[];
    const uint32_t sb = smem_u32(smem);
    const int tid    = threadIdx.x;
    const int lane   = tid & 31;
    const int wid    = tid >> 5;
    const int warp_m = wid >> 2;          // 0..1
    const int warp_n = wid & 3;           // 0..3
    const int row0   = blockIdx.y * BM;
    const int n0     = blockIdx.x * BN;

    // A loader mapping: 1024 float4 over 256 threads, 4 each
    const int ar = tid >> 1;              // unused base; real mapping below per i
    (void)ar;

    float acc[4][4][4];
    #pragma unroll
    for (int mi = 0; mi < 4; mi++)
        #pragma unroll
        for (int ni = 0; ni < 4; ni++)
            #pragma unroll
            for (int j = 0; j < 4; j++) acc[mi][ni][j] = 0.f;

    float4 av[4];

    // ---- helpers as lambdas -------------------------------------------------
    auto loadA = [&](int kt) {
        const int k0 = kt * BK;
        #pragma unroll
        for (int i = 0; i < 4; i++) {
            int idx = i * THREADS + tid;      // 0..1023
            int r = idx >> 3;                 // 0..127
            int c = (idx & 7) << 2;           // 0..28
            int gr = row0 + r;
            av[i] = (gr < M) ? *reinterpret_cast<const float4*>(A + (size_t)gr * IN_DIM + k0 + c)
                             : make_float4(0.f, 0.f, 0.f, 0.f);
        }
    };
    auto stsA = [&](int st) {
        #pragma unroll
        for (int i = 0; i < 4; i++) {
            int idx = i * THREADS + tid;
            int r = idx >> 3;
            int c = (idx & 7) << 2;
            float4 v = av[i];
            __nv_bfloat16 hx = __float2bfloat16_rn(v.x), hy = __float2bfloat16_rn(v.y);
            __nv_bfloat16 hz = __float2bfloat16_rn(v.z), hw = __float2bfloat16_rn(v.w);
            __nv_bfloat16 lx = __float2bfloat16_rn(v.x - __bfloat162float(hx));
            __nv_bfloat16 ly = __float2bfloat16_rn(v.y - __bfloat162float(hy));
            __nv_bfloat16 lz = __float2bfloat16_rn(v.z - __bfloat162float(hz));
            __nv_bfloat16 lw = __float2bfloat16_rn(v.w - __bfloat162float(hw));
            uint2 h, l;
            h.x = ((uint32_t)__bfloat16_as_ushort(hy) << 16) | __bfloat16_as_ushort(hx);
            h.y = ((uint32_t)__bfloat16_as_ushort(hw) << 16) | __bfloat16_as_ushort(hz);
            l.x = ((uint32_t)__bfloat16_as_ushort(ly) << 16) | __bfloat16_as_ushort(lx);
            l.y = ((uint32_t)__bfloat16_as_ushort(lw) << 16) | __bfloat16_as_ushort(lz);
            char* base = smem + st * STAGE + r * ROWB + c * 2;
            *reinterpret_cast<uint2*>(base + A_HI) = h;
            *reinterpret_cast<uint2*>(base + A_LO) = l;
        }
    };
    auto issueB = [&](int kt, int st) {
        const int k0 = kt * BK;
        #pragma unroll
        for (int i = 0; i < 2; i++) {
            int idx = i * THREADS + tid;      // 0..511
            int r = idx >> 2;                 // 0..127
            int u = idx & 3;                  // 16B unit
            size_t gofs = (size_t)(n0 + r) * IN_DIM + k0 + u * 8;
            uint32_t dst = sb + st * STAGE + r * ROWB + u * 16;
            cp16(dst + B_HI, g_Whi + gofs);
            cp16(dst + B_LO, g_Wlo + gofs);
        }
        asm volatile("cp.async.commit_group;" ::: "memory");
    };

    // ---- prologue -----------------------------------------------------------
    loadA(0);
    issueB(0, 0);
    stsA(0);
    asm volatile("cp.async.wait_group 0;" ::: "memory");
    __syncthreads();

    // ---- main loop ----------------------------------------------------------
    for (int kt = 0; kt < NCHUNK; kt++) {
        const int st = kt & 1;
        const bool pf = (kt + 1) < NCHUNK;
        if (pf) { loadA(kt + 1); issueB(kt + 1, st ^ 1); }

        const uint32_t sbase = sb + st * STAGE;
        #pragma unroll
        for (int s = 0; s < 2; s++) {
            const int k0 = s * 16;
            const uint32_t acol = (uint32_t)(k0 + ((lane >> 4) << 3)) * 2;
            const uint32_t arow = (uint32_t)(warp_m * 64 + (lane & 15));
            const uint32_t bcol = (uint32_t)(k0 + ((lane >> 3) & 1) * 8) * 2;
            const uint32_t brow = (uint32_t)(warp_n * 32 + (lane & 7));

            uint32_t ah[4][4], al[4][4], bh[4][2], bl[4][2];
            #pragma unroll
            for (int mi = 0; mi < 4; mi++) {
                uint32_t ad = sbase + A_HI + (arow + mi * 16) * ROWB + acol;
                ldx4(ah[mi], ad);
            }
            #pragma unroll
            for (int ni = 0; ni < 4; ni++) {
                uint32_t bd = sbase + B_HI + (brow + ni * 8) * ROWB + bcol;
                ldx2(bh[ni], bd);
            }
            // hi x hi
            #pragma unroll
            for (int mi = 0; mi < 4; mi++)
                #pragma unroll
                for (int ni = 0; ni < 4; ni++)
                    mma16816(acc[mi][ni], ah[mi], bh[ni]);
            // lo x hi
            #pragma unroll
            for (int mi = 0; mi < 4; mi++) {
                uint32_t ad = sbase + A_LO + (arow + mi * 16) * ROWB + acol;
                ldx4(al[mi], ad);
            }
            #pragma unroll
            for (int mi = 0; mi < 4; mi++)
                #pragma unroll
                for (int ni = 0; ni < 4; ni++)
                    mma16816(acc[mi][ni], al[mi], bh[ni]);
            // hi x lo
            #pragma unroll
            for (int ni = 0; ni < 4; ni++) {
                uint32_t bd = sbase + B_LO + (brow + ni * 8) * ROWB + bcol;
                ldx2(bl[ni], bd);
            }
            #pragma unroll
            for (int mi = 0; mi < 4; mi++)
                #pragma unroll
                for (int ni = 0; ni < 4; ni++)
                    mma16816(acc[mi][ni], ah[mi], bl[ni]);
        }

        if (pf) stsA(st ^ 1);
        asm volatile("cp.async.wait_group 0;" ::: "memory");
        __syncthreads();
    }

    // ---- epilogue: bias + relu + float2 stores ------------------------------
    #pragma unroll
    for (int mi = 0; mi < 4; mi++) {
        int r = row0 + warp_m * 64 + mi * 16 + (lane >> 2);
        #pragma unroll
        for (int ni = 0; ni < 4; ni++) {
            int col = n0 + warp_n * 32 + ni * 8 + (lane & 3) * 2;
            float2 bv = *reinterpret_cast<const float2*>(bias + col);
            if (r < M) {
                float2 o;
                o.x = fmaxf(acc[mi][ni][0] + bv.x, 0.f);
                o.y = fmaxf(acc[mi][ni][1] + bv.y, 0.f);
                *reinterpret_cast<float2*>(C + (size_t)r * OUT_DIM + col) = o;
            }
            if (r + 8 < M) {
                float2 o;
                o.x = fmaxf(acc[mi][ni][2] + bv.x, 0.f);
                o.y = fmaxf(acc[mi][ni][3] + bv.y, 0.f);
                *reinterpret_cast<float2*>(C + (size_t)(r + 8) * OUT_DIM + col) = o;
            }
        }
    }
}

// ---------------- scatter-add on column 0 -------------------------------------
__global__ void scatter_add_col0_kernel(const float* __restrict__ x,
                                        const int* __restrict__ edge_index,
                                        float* __restrict__ out,
                                        int E) {
    int e = blockIdx.x * blockDim.x + threadIdx.x;
    if (e < E) {
        int c = edge_index[E + e];            // row 1 of [2,E] int32
        atomicAdd(&out[(size_t)c * OUT_DIM], x[(size_t)e * IN_DIM]);
    }
}

// ---------------- launch ------------------------------------------------------
extern "C" void kernel_launch(void* const* d_in, const int* in_sizes, int n_in,
                              void* d_out, int out_size) {
    const float* x   = (const float*)d_in[0];
    const int*   ei  = (const int*)d_in[1];
    const float* W   = (const float*)d_in[2];
    const float* b   = (const float*)d_in[3];
    float*       out = (float*)d_out;

    const int M = in_sizes[0] / IN_DIM;
    const int E = in_sizes[1] / 2;

    cudaFuncSetAttribute(gemm_mma_kernel, cudaFuncAttributeMaxDynamicSharedMemorySize, SM_TOTAL);

    split_W_kernel<<<(OUT_DIM * IN_DIM + 255) / 256, 256>>>(W);

    dim3 grid(OUT_DIM / BN, (M + BM - 1) / BM);   // x = N tiles (L2 reuse of A band)
    gemm_mma_kernel<<<grid, THREADS, SM_TOTAL>>>(x, b, out, M);

    scatter_add_col0_kernel<<<(E + 255) / 256, 256>>>(x, ei, out, E);
}